// round 1
// baseline (speedup 1.0000x reference)
#include <cuda_runtime.h>
#include <math.h>

#define B_ROWS 8192
#define D 512
#define NTHETA 608
#define NFORE (NTHETA - D)
#define NEXP 8
#define MAXP (B_ROWS * 2)

// ---------------- device scratch (static; no allocations allowed) ----------
__device__ int   g_count[NEXP];
__device__ int   g_offset[NEXP];
__device__ int   g_cursor[NEXP];
__device__ int   g_token[MAXP];        // packed pair -> token id
__device__ int   g_slot[B_ROWS][2];    // token,k -> packed pair (temp: expert id)
__device__ float g_gw[B_ROWS][2];      // gate weights
__device__ float g_buf0[MAXP * D];
__device__ float g_buf1[MAXP * D];
__device__ float g_theta[MAXP * NTHETA];

// ---------------- reset ----------------------------------------------------
__global__ void zero_kernel() {
    if (threadIdx.x < NEXP) g_count[threadIdx.x] = 0;
}

// ---------------- gate: layernorm + logits + top2 + softmax ----------------
__global__ void gate_kernel(const float* __restrict__ x,
                            const float* __restrict__ gamma,
                            const float* __restrict__ beta,
                            const float* __restrict__ Wg) {
    int row = blockIdx.x;
    const float* xr = x + (size_t)row * D;
    __shared__ float sx[D];
    __shared__ float ws[8], ws2[8];
    __shared__ float smu, srstd;
    __shared__ float logits[NEXP];

    int tid = threadIdx.x;  // 256 threads
    float v0 = xr[tid], v1 = xr[tid + 256];
    sx[tid] = v0; sx[tid + 256] = v1;
    float s  = v0 + v1;
    float s2 = v0 * v0 + v1 * v1;
    #pragma unroll
    for (int o = 16; o; o >>= 1) {
        s  += __shfl_down_sync(0xFFFFFFFFu, s,  o);
        s2 += __shfl_down_sync(0xFFFFFFFFu, s2, o);
    }
    if ((tid & 31) == 0) { ws[tid >> 5] = s; ws2[tid >> 5] = s2; }
    __syncthreads();
    if (tid == 0) {
        float a = 0.f, b = 0.f;
        #pragma unroll
        for (int i = 0; i < 8; i++) { a += ws[i]; b += ws2[i]; }
        float mu  = a / (float)D;
        float var = b / (float)D - mu * mu;
        smu = mu;
        srstd = rsqrtf(var + 1e-5f);
    }
    __syncthreads();
    float mu = smu, rstd = srstd;

    // one warp per expert
    int e = tid >> 5, lane = tid & 31;
    float acc = 0.f;
    for (int i = lane; i < D; i += 32) {
        float xn = (sx[i] - mu) * rstd * gamma[i] + beta[i];
        acc += xn * Wg[i * NEXP + e];
    }
    #pragma unroll
    for (int o = 16; o; o >>= 1) acc += __shfl_down_sync(0xFFFFFFFFu, acc, o);
    if (lane == 0) logits[e] = acc;
    __syncthreads();

    if (tid == 0) {
        int i0 = 0; float v0l = logits[0];
        #pragma unroll
        for (int i = 1; i < NEXP; i++) if (logits[i] > v0l) { v0l = logits[i]; i0 = i; }
        int i1 = -1; float v1l = -1e30f;
        #pragma unroll
        for (int i = 0; i < NEXP; i++) {
            if (i == i0) continue;
            if (logits[i] > v1l) { v1l = logits[i]; i1 = i; }
        }
        float e1 = __expf(v1l - v0l);
        float inv = 1.f / (1.f + e1);
        g_gw[row][0] = inv;
        g_gw[row][1] = e1 * inv;
        g_slot[row][0] = i0;
        g_slot[row][1] = i1;
        atomicAdd(&g_count[i0], 1);
        atomicAdd(&g_count[i1], 1);
    }
}

// ---------------- prefix + slot assignment ---------------------------------
__global__ void prefix_kernel() {
    int off = 0;
    for (int e = 0; e < NEXP; e++) {
        g_offset[e] = off;
        g_cursor[e] = off;
        off += g_count[e];
    }
}

__global__ void assign_kernel() {
    int row = blockIdx.x * blockDim.x + threadIdx.x;
    if (row >= B_ROWS) return;
    #pragma unroll
    for (int k = 0; k < 2; k++) {
        int e = g_slot[row][k];
        int p = atomicAdd(&g_cursor[e], 1);
        g_token[p] = row;
        g_slot[row][k] = p;
    }
}

// ---------------- grouped SGEMM --------------------------------------------
// C[pair, N] = A[pair, K=512] * W[e, K, N]  (optionally relu)
// asel: 0 = gather from x via g_token, 1 = g_buf0, 2 = g_buf1
// csel: 0 = g_buf0, 1 = g_buf1, 2 = g_theta
__global__ __launch_bounds__(256)
void gemm_kernel(const float* __restrict__ X, const float* __restrict__ W,
                 int asel, int csel, int N, int relu) {
    const int BM = 128, BN = 128, BK = 8;
    int e = blockIdx.z;
    int cnt = g_count[e];
    int m0 = blockIdx.y * BM;
    if (m0 >= cnt) return;
    int n0 = blockIdx.x * BN;
    int base = g_offset[e];
    const float* Wp = W + (size_t)e * D * N;

    const float* A = (asel == 0) ? X : (asel == 1 ? g_buf0 : g_buf1);
    float* C = (csel == 0) ? g_buf0 : (csel == 1 ? g_buf1 : g_theta);

    __shared__ __align__(16) float As[BK][BM];
    __shared__ __align__(16) float Bs[BK][BN];

    int tid = threadIdx.x;  // 256
    float acc[8][8];
    #pragma unroll
    for (int i = 0; i < 8; i++)
        #pragma unroll
        for (int j = 0; j < 8; j++) acc[i][j] = 0.f;

    // A tile loads: 128x8 floats, 2 threads per row, float4 along K
    int arow = tid >> 1;
    int acol = (tid & 1) * 4;
    // B tile loads: 8x128 floats, 32 threads per row, float4 along N
    int brow = tid >> 5;
    int bcol = (tid & 31) * 4;
    // microtile position
    int tm = (tid >> 4) * 8;
    int tn = (tid & 15) * 8;

    int gm_load = m0 + arow;
    const float* arow_ptr = nullptr;
    if (gm_load < cnt) {
        int srcrow = (asel == 0) ? g_token[base + gm_load] : (base + gm_load);
        arow_ptr = A + (size_t)srcrow * D + acol;
    }
    int gn_load = n0 + bcol;
    bool bvalid = (gn_load < N);
    const float* brow_ptr = Wp + (size_t)brow * N + gn_load;

    for (int k0 = 0; k0 < D; k0 += BK) {
        float4 av = make_float4(0.f, 0.f, 0.f, 0.f);
        if (arow_ptr) av = *reinterpret_cast<const float4*>(arow_ptr + k0);
        As[acol + 0][arow] = av.x;
        As[acol + 1][arow] = av.y;
        As[acol + 2][arow] = av.z;
        As[acol + 3][arow] = av.w;

        float4 bv = make_float4(0.f, 0.f, 0.f, 0.f);
        if (bvalid) bv = *reinterpret_cast<const float4*>(brow_ptr + (size_t)k0 * N);
        *reinterpret_cast<float4*>(&Bs[brow][bcol]) = bv;
        __syncthreads();

        #pragma unroll
        for (int k = 0; k < BK; k++) {
            float a[8], b[8];
            *(float4*)(a)     = *(const float4*)&As[k][tm];
            *(float4*)(a + 4) = *(const float4*)&As[k][tm + 4];
            *(float4*)(b)     = *(const float4*)&Bs[k][tn];
            *(float4*)(b + 4) = *(const float4*)&Bs[k][tn + 4];
            #pragma unroll
            for (int i = 0; i < 8; i++)
                #pragma unroll
                for (int j = 0; j < 8; j++)
                    acc[i][j] += a[i] * b[j];
        }
        __syncthreads();
    }

    #pragma unroll
    for (int i = 0; i < 8; i++) {
        int gm = m0 + tm + i;
        if (gm >= cnt) continue;
        float* crow = C + (size_t)(base + gm) * N;
        #pragma unroll
        for (int j = 0; j < 8; j += 4) {
            int gn = n0 + tn + j;
            if (gn < N) {
                float4 v = make_float4(acc[i][j], acc[i][j + 1], acc[i][j + 2], acc[i][j + 3]);
                if (relu) {
                    v.x = fmaxf(v.x, 0.f); v.y = fmaxf(v.y, 0.f);
                    v.z = fmaxf(v.z, 0.f); v.w = fmaxf(v.w, 0.f);
                }
                *reinterpret_cast<float4*>(crow + gn) = v;
            }
        }
    }
}

// ---------------- combine: weighted sum of the 2 selected thetas -----------
__global__ void combine_kernel(float* __restrict__ out) {
    int row = blockIdx.x;
    int p0 = g_slot[row][0], p1 = g_slot[row][1];
    float w0 = g_gw[row][0], w1 = g_gw[row][1];
    const float* t0 = g_theta + (size_t)p0 * NTHETA;
    const float* t1 = g_theta + (size_t)p1 * NTHETA;
    for (int t = threadIdx.x; t < NTHETA; t += blockDim.x) {
        float v = w0 * t0[t] + w1 * t1[t];
        if (t < D) out[(size_t)row * D + t] = v;
        else       out[(size_t)B_ROWS * D + (size_t)row * NFORE + (t - D)] = v;
    }
}

// ---------------- launch ----------------------------------------------------
extern "C" void kernel_launch(void* const* d_in, const int* in_sizes, int n_in,
                              void* d_out, int out_size) {
    const float* x     = (const float*)d_in[0];
    const float* gamma = (const float*)d_in[1];
    const float* beta  = (const float*)d_in[2];
    const float* Wg    = (const float*)d_in[3];
    const float* W0    = (const float*)d_in[4];
    const float* Wmid  = (const float*)d_in[5];
    const float* Wout  = (const float*)d_in[6];
    float* out = (float*)d_out;

    zero_kernel<<<1, 32>>>();
    gate_kernel<<<B_ROWS, 256>>>(x, gamma, beta, Wg);
    prefix_kernel<<<1, 1>>>();
    assign_kernel<<<B_ROWS / 256, 256>>>();

    dim3 blk(256);
    dim3 g512(4, 64, NEXP);    // N=512 -> 4 tiles of 128
    dim3 g608(5, 64, NEXP);    // N=608 -> 5 tiles of 128

    const size_t WMID_STRIDE = (size_t)NEXP * D * D;
    // z = x @ W0           (gather, no relu)  -> buf0
    gemm_kernel<<<g512, blk>>>(x, W0, 0, 0, D, 0);
    // z = relu(z @ Wmid0)  -> buf1
    gemm_kernel<<<g512, blk>>>(nullptr, Wmid + 0 * WMID_STRIDE, 1, 1, D, 1);
    // z = relu(z @ Wmid1)  -> buf0
    gemm_kernel<<<g512, blk>>>(nullptr, Wmid + 1 * WMID_STRIDE, 2, 0, D, 1);
    // z = relu(z @ Wmid2)  -> buf1
    gemm_kernel<<<g512, blk>>>(nullptr, Wmid + 2 * WMID_STRIDE, 1, 1, D, 1);
    // theta = z @ Wout     -> theta
    gemm_kernel<<<g608, blk>>>(nullptr, Wout, 2, 2, NTHETA, 0);

    combine_kernel<<<B_ROWS, 256>>>(out);
}

// round 6
// speedup vs baseline: 2.1507x; 2.1507x over previous
#include <cuda_runtime.h>
#include <cuda_bf16.h>
#include <stdint.h>
#include <math.h>

#define B_ROWS 8192
#define D 512
#define NTHETA 608
#define NFORE (NTHETA - D)
#define NEXP 8
#define MAXP (B_ROWS * 2)
#define NCHUNK 8            // K=512 / 64
#define STAGE_BYTES 65536   // 4 tiles x 16KB
#define GEMM_SMEM (1024 + 2 * STAGE_BYTES)

// ---------------- device scratch ----------------
__device__ int   g_count[NEXP];
__device__ int   g_offset[NEXP];
__device__ int   g_cursor[NEXP];
__device__ int   g_token[MAXP];
__device__ int   g_slot[B_ROWS][2];
__device__ float g_gw[B_ROWS][2];

__device__ __nv_bfloat16 g_xh[B_ROWS * D],  g_xl[B_ROWS * D];
__device__ __nv_bfloat16 g_W0h[NEXP * D * D], g_W0l[NEXP * D * D];          // [e][n][k]
__device__ __nv_bfloat16 g_Wmh[3 * NEXP * D * D], g_Wml[3 * NEXP * D * D];  // [l*8+e][n][k]
__device__ __nv_bfloat16 g_Woh[NEXP * NTHETA * D], g_Wol[NEXP * NTHETA * D];// [e][n][k]
__device__ __nv_bfloat16 g_a0h[MAXP * D], g_a0l[MAXP * D];
__device__ __nv_bfloat16 g_a1h[MAXP * D], g_a1l[MAXP * D];
__device__ float g_theta[MAXP * NTHETA];

// ---------------- helpers ----------------
__device__ __forceinline__ uint32_t smem_u32(const void* p) {
    uint32_t a;
    asm("{ .reg .u64 t; cvta.to.shared.u64 t, %1; cvt.u32.u64 %0, t; }" : "=r"(a) : "l"(p));
    return a;
}
__device__ __forceinline__ void cpa16(uint32_t s, const void* g) {
    asm volatile("cp.async.ca.shared.global [%0], [%1], 16;" :: "r"(s), "l"(g) : "memory");
}
__device__ __forceinline__ void ldx4(uint32_t* r, uint32_t addr) {
    asm volatile("ldmatrix.sync.aligned.m8n8.x4.shared.b16 {%0,%1,%2,%3}, [%4];"
                 : "=r"(r[0]), "=r"(r[1]), "=r"(r[2]), "=r"(r[3]) : "r"(addr));
}
__device__ __forceinline__ void mma16816(float* d, const uint32_t* a, const uint32_t* b) {
    asm volatile(
        "mma.sync.aligned.m16n8k16.row.col.f32.bf16.bf16.f32 "
        "{%0,%1,%2,%3}, {%4,%5,%6,%7}, {%8,%9}, {%0,%1,%2,%3};"
        : "+f"(d[0]), "+f"(d[1]), "+f"(d[2]), "+f"(d[3])
        : "r"(a[0]), "r"(a[1]), "r"(a[2]), "r"(a[3]), "r"(b[0]), "r"(b[1]));
}
__device__ __forceinline__ void split2(float v, __nv_bfloat16& h, __nv_bfloat16& l) {
    h = __float2bfloat16(v);
    l = __float2bfloat16(v - __bfloat162float(h));
}

// ---------------- reset ----------------
__global__ void zero_kernel() {
    if (threadIdx.x < NEXP) g_count[threadIdx.x] = 0;
}

// ---------------- gate ----------------
__global__ void gate_kernel(const float* __restrict__ x,
                            const float* __restrict__ gamma,
                            const float* __restrict__ beta,
                            const float* __restrict__ Wg) {
    int row = blockIdx.x;
    const float* xr = x + (size_t)row * D;
    __shared__ float sx[D];
    __shared__ float ws[8], ws2[8];
    __shared__ float smu, srstd;
    __shared__ float logits[NEXP];

    int tid = threadIdx.x;
    float v0 = xr[tid], v1 = xr[tid + 256];
    sx[tid] = v0; sx[tid + 256] = v1;
    float s  = v0 + v1;
    float s2 = v0 * v0 + v1 * v1;
    #pragma unroll
    for (int o = 16; o; o >>= 1) {
        s  += __shfl_down_sync(0xFFFFFFFFu, s,  o);
        s2 += __shfl_down_sync(0xFFFFFFFFu, s2, o);
    }
    if ((tid & 31) == 0) { ws[tid >> 5] = s; ws2[tid >> 5] = s2; }
    __syncthreads();
    if (tid == 0) {
        float a = 0.f, b = 0.f;
        #pragma unroll
        for (int i = 0; i < 8; i++) { a += ws[i]; b += ws2[i]; }
        float mu  = a / (float)D;
        float var = b / (float)D - mu * mu;
        smu = mu;
        srstd = rsqrtf(var + 1e-5f);
    }
    __syncthreads();
    float mu = smu, rstd = srstd;

    int e = tid >> 5, lane = tid & 31;
    float acc = 0.f;
    for (int i = lane; i < D; i += 32) {
        float xn = (sx[i] - mu) * rstd * gamma[i] + beta[i];
        acc += xn * Wg[i * NEXP + e];
    }
    #pragma unroll
    for (int o = 16; o; o >>= 1) acc += __shfl_down_sync(0xFFFFFFFFu, acc, o);
    if (lane == 0) logits[e] = acc;
    __syncthreads();

    if (tid == 0) {
        int i0 = 0; float v0l = logits[0];
        #pragma unroll
        for (int i = 1; i < NEXP; i++) if (logits[i] > v0l) { v0l = logits[i]; i0 = i; }
        int i1 = -1; float v1l = -1e30f;
        #pragma unroll
        for (int i = 0; i < NEXP; i++) {
            if (i == i0) continue;
            if (logits[i] > v1l) { v1l = logits[i]; i1 = i; }
        }
        float e1 = __expf(v1l - v0l);
        float inv = 1.f / (1.f + e1);
        g_gw[row][0] = inv;
        g_gw[row][1] = e1 * inv;
        g_slot[row][0] = i0;
        g_slot[row][1] = i1;
        atomicAdd(&g_count[i0], 1);
        atomicAdd(&g_count[i1], 1);
    }
}

__global__ void prefix_kernel() {
    int off = 0;
    for (int e = 0; e < NEXP; e++) {
        g_offset[e] = off;
        g_cursor[e] = off;
        off += g_count[e];
    }
}

__global__ void assign_kernel() {
    int row = blockIdx.x * blockDim.x + threadIdx.x;
    if (row >= B_ROWS) return;
    #pragma unroll
    for (int k = 0; k < 2; k++) {
        int e = g_slot[row][k];
        int p = atomicAdd(&g_cursor[e], 1);
        g_token[p] = row;
        g_slot[row][k] = p;
    }
}

// ---------------- one-time splits ----------------
__global__ void xsplit_kernel(const float* __restrict__ x) {
    int i = blockIdx.x * blockDim.x + threadIdx.x;
    float v = x[i];
    __nv_bfloat16 h, l;
    split2(v, h, l);
    g_xh[i] = h; g_xl[i] = l;
}

// transpose+split: src [mat][K][N] fp32 -> dst[dsel] [mat][N][K] bf16 hi/lo
// dsel: 0 = W0, 1 = Wmid, 2 = Wout   (device symbols resolved in device code!)
__global__ void tsplit_kernel(const float* __restrict__ src, int dsel, int K, int N) {
    __shared__ float t[32][33];
    int mat = blockIdx.z;
    const float* s = src + (size_t)mat * K * N;
    int n0 = blockIdx.x * 32, k0 = blockIdx.y * 32;
    int tx = threadIdx.x, ty = threadIdx.y;   // 32x8
    #pragma unroll
    for (int i = 0; i < 32; i += 8) {
        int k = k0 + ty + i, n = n0 + tx;
        t[ty + i][tx] = (k < K && n < N) ? s[(size_t)k * N + n] : 0.f;
    }
    __syncthreads();
    __nv_bfloat16* dh = (dsel == 0) ? g_W0h : (dsel == 1 ? g_Wmh : g_Woh);
    __nv_bfloat16* dl = (dsel == 0) ? g_W0l : (dsel == 1 ? g_Wml : g_Wol);
    __nv_bfloat16* oh = dh + (size_t)mat * N * K;
    __nv_bfloat16* ol = dl + (size_t)mat * N * K;
    #pragma unroll
    for (int i = 0; i < 32; i += 8) {
        int n = n0 + ty + i, k = k0 + tx;
        if (n < N && k < K) {
            __nv_bfloat16 h, l;
            split2(t[tx][ty + i], h, l);
            oh[(size_t)n * K + k] = h;
            ol[(size_t)n * K + k] = l;
        }
    }
}

// ---------------- HMMA grouped GEMM ----------------
// asel: 0 = x (gather via g_token), 1 = a0, 2 = a1
// bsel: 0 = W0, 1..3 = Wmid layer, 4 = Wout
// csel: 0 = a0, 1 = a1, 2 = theta (fp32)
__global__ __launch_bounds__(256, 1)
void moe_gemm(int asel, int bsel, int csel, int Nfull, int relu) {
    extern __shared__ char smem[];
    int e = blockIdx.z;
    int cnt = g_count[e];
    int m0 = blockIdx.y * 128;
    if (m0 >= cnt) return;
    int n0 = blockIdx.x * 128;
    int base = g_offset[e];

    const __nv_bfloat16 *Ah, *Al;
    if (asel == 0)      { Ah = g_xh;  Al = g_xl;  }
    else if (asel == 1) { Ah = g_a0h; Al = g_a0l; }
    else                { Ah = g_a1h; Al = g_a1l; }
    const __nv_bfloat16 *Bh, *Bl;
    if (bsel == 0)      { Bh = g_W0h; Bl = g_W0l; }
    else if (bsel <= 3) {
        size_t off = (size_t)(bsel - 1) * NEXP * D * D;
        Bh = g_Wmh + off; Bl = g_Wml + off;
    } else              { Bh = g_Woh; Bl = g_Wol; }
    int gather = (asel == 0);
    int mode   = (csel == 2);
    __nv_bfloat16* Ch = (csel == 0) ? g_a0h : g_a1h;
    __nv_bfloat16* Cl = (csel == 0) ? g_a0l : g_a1l;

    uint32_t sb = smem_u32(smem);
    uint32_t tiles = (sb + 1023) & ~1023u;

    int tid = threadIdx.x;
    int wid = tid >> 5, lid = tid & 31;
    int wm = wid >> 2, wn = wid & 3;   // 2 x 4 warps

    // ---- loader mapping: each thread owns one 64B half-row per tile ----
    int lrow  = tid >> 1;
    int lhalf = (tid & 1) * 64;
    int am = m0 + lrow; if (am >= cnt) am = 0;
    int arow = gather ? g_token[base + am] : (base + am);
    int bn = n0 + lrow; if (bn >= Nfull) bn = 0;
    const char* pAh = (const char*)Ah + (size_t)arow * (D * 2) + lhalf;
    const char* pAl = (const char*)Al + (size_t)arow * (D * 2) + lhalf;
    const char* pBh = (const char*)(Bh + (size_t)e * Nfull * D) + (size_t)bn * (D * 2) + lhalf;
    const char* pBl = (const char*)(Bl + (size_t)e * Nfull * D) + (size_t)bn * (D * 2) + lhalf;
    uint32_t xr  = (uint32_t)(lrow & 7) << 4;
    uint32_t so0 = (uint32_t)lrow * 128;

    // ---- ldmatrix lane mapping ----
    int q = lid >> 3, r = lid & 7;
    uint32_t arow_q  = (uint32_t)((q & 1) * 8 + r);
    uint32_t abyte_q = (uint32_t)((q >> 1) * 16);
    uint32_t brow_q  = (uint32_t)((q >> 1) * 8 + r);
    uint32_t bbyte_q = (uint32_t)((q & 1) * 16);
    uint32_t lxor    = (uint32_t)r << 4;
    uint32_t m_warp  = (uint32_t)(wm * 64);
    uint32_t n_warp  = (uint32_t)(wn * 32);

    float acc[4][4][4];
    #pragma unroll
    for (int i = 0; i < 4; i++)
        #pragma unroll
        for (int j = 0; j < 4; j++)
            #pragma unroll
            for (int k = 0; k < 4; k++) acc[i][j][k] = 0.f;

    // ---- prologue: stage 0 ----
    {
        uint32_t st = tiles;
        #pragma unroll
        for (int i = 0; i < 4; i++) {
            uint32_t so = so0 + (((uint32_t)lhalf + i * 16) ^ xr);
            cpa16(st +     0 + so, pAh + i * 16);
            cpa16(st + 16384 + so, pAl + i * 16);
            cpa16(st + 32768 + so, pBh + i * 16);
            cpa16(st + 49152 + so, pBl + i * 16);
        }
        asm volatile("cp.async.commit_group;" ::: "memory");
    }

    #pragma unroll 1
    for (int c = 0; c < NCHUNK; c++) {
        if (c < NCHUNK - 1) {
            uint32_t st = tiles + ((c + 1) & 1) * STAGE_BYTES;
            size_t goff = (size_t)(c + 1) * 128;
            #pragma unroll
            for (int i = 0; i < 4; i++) {
                uint32_t so = so0 + (((uint32_t)lhalf + i * 16) ^ xr);
                cpa16(st +     0 + so, pAh + goff + i * 16);
                cpa16(st + 16384 + so, pAl + goff + i * 16);
                cpa16(st + 32768 + so, pBh + goff + i * 16);
                cpa16(st + 49152 + so, pBl + goff + i * 16);
            }
            asm volatile("cp.async.commit_group;" ::: "memory");
            asm volatile("cp.async.wait_group 1;" ::: "memory");
        } else {
            asm volatile("cp.async.wait_group 0;" ::: "memory");
        }
        __syncthreads();

        uint32_t st = tiles + (c & 1) * STAGE_BYTES;
        uint32_t sAh = st, sAl = st + 16384, sBh = st + 32768, sBl = st + 49152;

        #pragma unroll
        for (int kk = 0; kk < 4; kk++) {
            uint32_t ah[16], al[16], bh[8], bl[8];
            #pragma unroll
            for (int mt = 0; mt < 4; mt++) {
                uint32_t ro = (m_warp + (uint32_t)(mt * 16) + arow_q) * 128;
                uint32_t co = ((uint32_t)(kk * 32) + abyte_q) ^ lxor;
                ldx4(ah + mt * 4, sAh + ro + co);
                ldx4(al + mt * 4, sAl + ro + co);
            }
            #pragma unroll
            for (int g2 = 0; g2 < 2; g2++) {
                uint32_t ro = (n_warp + (uint32_t)(g2 * 16) + brow_q) * 128;
                uint32_t co = ((uint32_t)(kk * 32) + bbyte_q) ^ lxor;
                ldx4(bh + g2 * 4, sBh + ro + co);
                ldx4(bl + g2 * 4, sBl + ro + co);
            }
            #pragma unroll
            for (int mt = 0; mt < 4; mt++) {
                #pragma unroll
                for (int nt = 0; nt < 4; nt++) {
                    const uint32_t* bph = bh + (nt >> 1) * 4 + (nt & 1) * 2;
                    const uint32_t* bpl = bl + (nt >> 1) * 4 + (nt & 1) * 2;
                    mma16816(acc[mt][nt], ah + mt * 4, bph);
                    mma16816(acc[mt][nt], ah + mt * 4, bpl);
                    mma16816(acc[mt][nt], al + mt * 4, bph);
                }
            }
        }
        __syncthreads();
    }

    // ---- epilogue ----
    int g = lid >> 2, tig = lid & 3;
    #pragma unroll
    for (int mt = 0; mt < 4; mt++) {
        #pragma unroll
        for (int half = 0; half < 2; half++) {
            int m = m0 + (int)m_warp + mt * 16 + g + half * 8;
            if (m >= cnt) continue;
            size_t orow = (size_t)(base + m);
            #pragma unroll
            for (int nt = 0; nt < 4; nt++) {
                int ncol = n0 + (int)n_warp + nt * 8 + tig * 2;
                float v0 = acc[mt][nt][half * 2 + 0];
                float v1 = acc[mt][nt][half * 2 + 1];
                if (mode == 0) {
                    if (relu) { v0 = fmaxf(v0, 0.f); v1 = fmaxf(v1, 0.f); }
                    __nv_bfloat16 h0, l0, h1, l1;
                    split2(v0, h0, l0);
                    split2(v1, h1, l1);
                    __nv_bfloat162 hp; hp.x = h0; hp.y = h1;
                    __nv_bfloat162 lp; lp.x = l0; lp.y = l1;
                    *(__nv_bfloat162*)(Ch + orow * D + ncol) = hp;
                    *(__nv_bfloat162*)(Cl + orow * D + ncol) = lp;
                } else {
                    if (ncol < NTHETA) {
                        float2 fv; fv.x = v0; fv.y = v1;
                        *(float2*)(g_theta + orow * NTHETA + ncol) = fv;
                    }
                }
            }
        }
    }
}

// ---------------- combine ----------------
__global__ void combine_kernel(float* __restrict__ out) {
    int row = blockIdx.x;
    int p0 = g_slot[row][0], p1 = g_slot[row][1];
    float w0 = g_gw[row][0], w1 = g_gw[row][1];
    const float* t0 = g_theta + (size_t)p0 * NTHETA;
    const float* t1 = g_theta + (size_t)p1 * NTHETA;
    for (int t = threadIdx.x; t < NTHETA; t += blockDim.x) {
        float v = w0 * t0[t] + w1 * t1[t];
        if (t < D) out[(size_t)row * D + t] = v;
        else       out[(size_t)B_ROWS * D + (size_t)row * NFORE + (t - D)] = v;
    }
}

// ---------------- launch ----------------
extern "C" void kernel_launch(void* const* d_in, const int* in_sizes, int n_in,
                              void* d_out, int out_size) {
    const float* x     = (const float*)d_in[0];
    const float* gamma = (const float*)d_in[1];
    const float* beta  = (const float*)d_in[2];
    const float* Wg    = (const float*)d_in[3];
    const float* W0    = (const float*)d_in[4];
    const float* Wmid  = (const float*)d_in[5];
    const float* Wout  = (const float*)d_in[6];
    float* out = (float*)d_out;

    cudaFuncSetAttribute(moe_gemm, cudaFuncAttributeMaxDynamicSharedMemorySize, GEMM_SMEM);

    zero_kernel<<<1, 32>>>();
    gate_kernel<<<B_ROWS, 256>>>(x, gamma, beta, Wg);
    prefix_kernel<<<1, 1>>>();
    assign_kernel<<<B_ROWS / 256, 256>>>();

    xsplit_kernel<<<(B_ROWS * D) / 256, 256>>>(x);
    dim3 tb(32, 8);
    tsplit_kernel<<<dim3(16, 16, NEXP), tb>>>(W0, 0, D, D);
    tsplit_kernel<<<dim3(16, 16, 3 * NEXP), tb>>>(Wmid, 1, D, D);
    tsplit_kernel<<<dim3(19, 16, NEXP), tb>>>(Wout, 2, D, NTHETA);

    dim3 blk(256);
    dim3 g512(4, 64, NEXP);
    dim3 g608(5, 64, NEXP);

    // asel, bsel, csel, Nfull, relu
    moe_gemm<<<g512, blk, GEMM_SMEM>>>(0, 0, 0, D, 0);       // x @ W0      -> a0
    moe_gemm<<<g512, blk, GEMM_SMEM>>>(1, 1, 1, D, 1);       // relu(a0@Wm0)-> a1
    moe_gemm<<<g512, blk, GEMM_SMEM>>>(2, 2, 0, D, 1);       // relu(a1@Wm1)-> a0
    moe_gemm<<<g512, blk, GEMM_SMEM>>>(1, 3, 1, D, 1);       // relu(a0@Wm2)-> a1
    moe_gemm<<<g608, blk, GEMM_SMEM>>>(2, 4, 2, NTHETA, 0);  // a1 @ Wout   -> theta

    combine_kernel<<<B_ROWS, 256>>>(out);
}